// round 1
// baseline (speedup 1.0000x reference)
#include <cuda_runtime.h>
#include <math_constants.h>

// Problem constants
#define BB   2
#define SS   2048
#define HH   8
#define DKK  512          // head dim
#define DMM  512          // model dim
#define HDIM 4096         // H * DKK
#define TT   (BB * SS)    // total tokens = 4096

// Scratch (static device memory — allocation-free per harness rules)
__device__ float g_q [(size_t)TT * HDIM];            // 67 MB  [t, h*DKK+e]
__device__ float g_k [(size_t)TT * HDIM];            // 67 MB
__device__ float g_v [(size_t)TT * HDIM];            // 67 MB
__device__ float g_ho[(size_t)TT * HDIM];            // 67 MB  heads_out [t, h*DKK+e]
__device__ float g_s [(size_t)BB * HH * SS * SS];    // 268 MB scores/probs [bh, s, t]

// ---------------------------------------------------------------------------
// Generic fp32 tile GEMM body: C[M,N](+=scale) = A[M,K] @ op(B)
//   BT=true : B is [N,K] row-major (NT gemm)
//   BT=false: B is [K,N] row-major (NN gemm)
// Block tile 128x128x32, 256 threads, 8x8 per-thread microtile with 4+4
// column split (cols tx*4..+3 and 64+tx*4..+3) for low-conflict smem reads.
// All dims in our calls are exact multiples of tile sizes -> no bounds checks.
// ---------------------------------------------------------------------------
template<bool BT, bool CAUSAL>
__device__ __forceinline__ void gemm_body(
    const float* __restrict__ A, int lda,
    const float* __restrict__ Bm, int ldb,
    float* __restrict__ C, int ldc,
    int kCount, float scale, int m0, int n0)
{
    constexpr int BM = 128, BN = 128, BK = 32;
    constexpr int BSTR = BT ? (BN + 1) : BN;

    __shared__ __align__(16) float As[BK][BM + 1];
    __shared__ __align__(16) float Bs[BK][BSTR];

    const int tid = threadIdx.x;
    const int tx  = tid & 15;   // column group (16)
    const int ty  = tid >> 4;   // row group (16)

    float acc[8][8];
#pragma unroll
    for (int i = 0; i < 8; i++)
#pragma unroll
        for (int j = 0; j < 8; j++) acc[i][j] = 0.0f;

    for (int k0 = 0; k0 < kCount; k0 += BK) {
        // --- load A tile [BM x BK], store transposed As[k][m] (pad 129: conflict-free)
#pragma unroll
        for (int i = 0; i < 4; i++) {
            int lin = tid + i * 256;
            int r   = lin >> 3;          // 0..127 (row m)
            int c   = (lin & 7) << 2;    // 0..28  (col k, x4)
            float4 v = *reinterpret_cast<const float4*>(
                A + (size_t)(m0 + r) * lda + k0 + c);
            As[c + 0][r] = v.x; As[c + 1][r] = v.y;
            As[c + 2][r] = v.z; As[c + 3][r] = v.w;
        }
        if (BT) {
            // B[N,K]: tile [BN x BK], store transposed Bs[k][n] (pad 129)
#pragma unroll
            for (int i = 0; i < 4; i++) {
                int lin = tid + i * 256;
                int r   = lin >> 3;        // 0..127 (row n)
                int c   = (lin & 7) << 2;  // k
                float4 v = *reinterpret_cast<const float4*>(
                    Bm + (size_t)(n0 + r) * ldb + k0 + c);
                Bs[c + 0][r] = v.x; Bs[c + 1][r] = v.y;
                Bs[c + 2][r] = v.z; Bs[c + 3][r] = v.w;
            }
        } else {
            // B[K,N]: tile [BK x BN], direct float4 store (stride 128, conflict-free)
#pragma unroll
            for (int i = 0; i < 4; i++) {
                int lin = tid + i * 256;
                int r   = lin >> 5;          // 0..31 (row k)
                int c   = (lin & 31) << 2;   // 0..124 (col n)
                float4 v = *reinterpret_cast<const float4*>(
                    Bm + (size_t)(k0 + r) * ldb + n0 + c);
                *reinterpret_cast<float4*>(&Bs[r][c]) = v;
            }
        }
        __syncthreads();

#pragma unroll 4
        for (int kk = 0; kk < BK; kk++) {
            float a[8], b[8];
#pragma unroll
            for (int i = 0; i < 8; i++) a[i] = As[kk][ty * 8 + i];
#pragma unroll
            for (int j = 0; j < 4; j++) {
                b[j]     = Bs[kk][tx * 4 + j];
                b[4 + j] = Bs[kk][64 + tx * 4 + j];
            }
#pragma unroll
            for (int i = 0; i < 8; i++)
#pragma unroll
                for (int j = 0; j < 8; j++)
                    acc[i][j] = fmaf(a[i], b[j], acc[i][j]);
        }
        __syncthreads();
    }

    // --- epilogue: scaled float4 stores, optional causal mask (col > row -> -inf)
#pragma unroll
    for (int i = 0; i < 8; i++) {
        int gr = m0 + ty * 8 + i;
#pragma unroll
        for (int g = 0; g < 2; g++) {
            int gc = n0 + g * 64 + tx * 4;
            float4 o;
            float* po = &o.x;
#pragma unroll
            for (int j = 0; j < 4; j++) {
                float v = acc[i][g * 4 + j] * scale;
                if (CAUSAL && (gc + j) > gr) v = -CUDART_INF_F;
                po[j] = v;
            }
            *reinterpret_cast<float4*>(C + (size_t)gr * ldc + gc) = o;
        }
    }
}

// ---------------------------------------------------------------------------
// Kernel 1: QKV projections. q/k/v[t, h*DKK+e] = x[t,:] . W[h*DKK+e, :]
// grid (32, 32, 3): z picks Wq/Wk/Wv and destination.
// ---------------------------------------------------------------------------
__global__ void __launch_bounds__(256, 2) k_qkv(
    const float* __restrict__ x,
    const float* __restrict__ Wq,
    const float* __restrict__ Wk,
    const float* __restrict__ Wv)
{
    int m0 = blockIdx.y * 128, n0 = blockIdx.x * 128;
    const float* W;
    float* Cc;
    if (blockIdx.z == 0)      { W = Wq; Cc = g_q; }
    else if (blockIdx.z == 1) { W = Wk; Cc = g_k; }
    else                      { W = Wv; Cc = g_v; }
    gemm_body<true, false>(x, DMM, W, DMM, Cc, HDIM, DMM, 1.0f, m0, n0);
}

// ---------------------------------------------------------------------------
// Kernel 2: masked attention scores. S[bh, s, t] = (q.k) * K^-0.5 , -inf if t>s
// grid (16, 16, 16). Fully-masked tiles (n0 >= m0+128) skip the GEMM.
// ---------------------------------------------------------------------------
__global__ void __launch_bounds__(256, 2) k_scores()
{
    int m0 = blockIdx.y * 128, n0 = blockIdx.x * 128;
    int bh = blockIdx.z;
    float* Cc = g_s + (size_t)bh * SS * SS;

    if (n0 >= m0 + 128) {
        // tile entirely above the diagonal: just write -inf
        int tx = threadIdx.x & 15, ty = threadIdx.x >> 4;
        float4 o = make_float4(-CUDART_INF_F, -CUDART_INF_F,
                               -CUDART_INF_F, -CUDART_INF_F);
#pragma unroll
        for (int i = 0; i < 8; i++) {
            int gr = m0 + ty * 8 + i;
#pragma unroll
            for (int g = 0; g < 2; g++) {
                int gc = n0 + g * 64 + tx * 4;
                *reinterpret_cast<float4*>(Cc + (size_t)gr * SS + gc) = o;
            }
        }
        return;
    }

    int b = bh / HH, h = bh % HH;
    const float* Aq = g_q + (size_t)b * SS * HDIM + h * DKK;
    const float* Bk = g_k + (size_t)b * SS * HDIM + h * DKK;
    // scale = K^-0.25 applied to both q and k  ==  K^-0.5 on the product
    gemm_body<true, true>(Aq, HDIM, Bk, HDIM, Cc, SS, DKK,
                          0.04419417382415922f, m0, n0);
}

// ---------------------------------------------------------------------------
// Kernel 3: row softmax over g_s rows (length 2048). Warp per row, 8 rows/CTA.
// grid = BB*HH*SS/8 = 4096, block 256.
// ---------------------------------------------------------------------------
__global__ void __launch_bounds__(256) k_softmax()
{
    int row  = blockIdx.x * 8 + (threadIdx.x >> 5);
    int lane = threadIdx.x & 31;
    float4* p = reinterpret_cast<float4*>(g_s + (size_t)row * SS);

    float4 v[16];
    float mx = -CUDART_INF_F;
#pragma unroll
    for (int i = 0; i < 16; i++) {
        v[i] = p[lane + i * 32];
        mx = fmaxf(mx, fmaxf(fmaxf(v[i].x, v[i].y), fmaxf(v[i].z, v[i].w)));
    }
#pragma unroll
    for (int o = 16; o; o >>= 1) mx = fmaxf(mx, __shfl_xor_sync(0xffffffffu, mx, o));

    float sum = 0.0f;
#pragma unroll
    for (int i = 0; i < 16; i++) {
        v[i].x = __expf(v[i].x - mx);
        v[i].y = __expf(v[i].y - mx);
        v[i].z = __expf(v[i].z - mx);
        v[i].w = __expf(v[i].w - mx);
        sum += (v[i].x + v[i].y) + (v[i].z + v[i].w);
    }
#pragma unroll
    for (int o = 16; o; o >>= 1) sum += __shfl_xor_sync(0xffffffffu, sum, o);

    float inv = 1.0f / sum;
#pragma unroll
    for (int i = 0; i < 16; i++) {
        v[i].x *= inv; v[i].y *= inv; v[i].z *= inv; v[i].w *= inv;
        p[lane + i * 32] = v[i];
    }
}

// ---------------------------------------------------------------------------
// Kernel 4: heads_out = P @ V (NN gemm). grid (4, 16, 16).
// k range clipped to m0+128 (probs are exactly 0 beyond the diagonal).
// ---------------------------------------------------------------------------
__global__ void __launch_bounds__(256, 2) k_pv()
{
    int m0 = blockIdx.y * 128, n0 = blockIdx.x * 128;
    int bh = blockIdx.z, b = bh / HH, h = bh % HH;
    const float* Ap = g_s  + (size_t)bh * SS * SS;
    const float* Bv = g_v  + (size_t)b * SS * HDIM + h * DKK;
    float*       Cc = g_ho + (size_t)b * SS * HDIM + h * DKK;
    int kCount = m0 + 128;  // causal: keys <= last row of this tile
    gemm_body<false, false>(Ap, SS, Bv, HDIM, Cc, HDIM, kCount, 1.0f, m0, n0);
}

// ---------------------------------------------------------------------------
// Kernel 5: out = heads_out @ Wu^T. grid (4, 32).
// ---------------------------------------------------------------------------
__global__ void __launch_bounds__(256, 2) k_out(
    const float* __restrict__ Wu, float* __restrict__ out)
{
    int m0 = blockIdx.y * 128, n0 = blockIdx.x * 128;
    gemm_body<true, false>(g_ho, HDIM, Wu, HDIM, out, DMM, HDIM, 1.0f, m0, n0);
}

// ---------------------------------------------------------------------------
extern "C" void kernel_launch(void* const* d_in, const int* in_sizes, int n_in,
                              void* d_out, int out_size)
{
    const float* x  = (const float*)d_in[0];
    const float* Wq = (const float*)d_in[1];
    const float* Wk = (const float*)d_in[2];
    const float* Wv = (const float*)d_in[3];
    const float* Wu = (const float*)d_in[4];
    float* out = (float*)d_out;

    dim3 blk(256);
    k_qkv    <<<dim3(HDIM / 128, TT / 128, 3),        blk>>>(x, Wq, Wk, Wv);
    k_scores <<<dim3(SS / 128, SS / 128, BB * HH),    blk>>>();
    k_softmax<<<BB * HH * SS / 8,                     256>>>();
    k_pv     <<<dim3(DKK / 128, SS / 128, BB * HH),   blk>>>();
    k_out    <<<dim3(DMM / 128, TT / 128, 1),         blk>>>(Wu, out);
}

// round 3
// speedup vs baseline: 2.0804x; 2.0804x over previous
#include <cuda_runtime.h>
#include <cuda_bf16.h>
#include <math_constants.h>
#include <cstdint>

#define BB 2
#define SS 2048
#define HH 8
#define DK 512
#define TT (BB*SS)      // 4096 tokens
#define NH (BB*HH)      // 16 (b,h) pairs

// ---------------- static device scratch (no allocs allowed) ----------------
__device__ __nv_bfloat16 g_xh[TT*DK],  g_xl[TT*DK];
__device__ __nv_bfloat16 g_wqh[4096*512], g_wql[4096*512];
__device__ __nv_bfloat16 g_wkh[4096*512], g_wkl[4096*512];
__device__ __nv_bfloat16 g_wvh[4096*512], g_wvl[4096*512];
__device__ __nv_bfloat16 g_wuh[512*4096], g_wul[512*4096];
__device__ __nv_bfloat16 g_qh[NH*SS*DK], g_ql[NH*SS*DK];
__device__ __nv_bfloat16 g_kh[NH*SS*DK], g_kl[NH*SS*DK];
__device__ __nv_bfloat16 g_vth[NH*DK*SS], g_vtl[NH*DK*SS];   // V transposed [bh][e][s]
__device__ float         g_s [(size_t)NH*SS*SS];             // fp32 scores
__device__ __nv_bfloat16 g_ph[(size_t)NH*SS*SS], g_pl[(size_t)NH*SS*SS];
__device__ __nv_bfloat16 g_hoh[(size_t)TT*4096], g_hol[(size_t)TT*4096];

// ---------------- helpers (baseline ISA only: ldmatrix + mma.sync) ---------
__device__ __forceinline__ uint32_t smem_u32(const void* p){
    uint32_t a; asm("{ .reg .u64 t; cvta.to.shared.u64 t, %1; cvt.u32.u64 %0, t; }":"=r"(a):"l"(p)); return a;
}
__device__ __forceinline__ uint32_t swz(uint32_t off){ return off ^ ((off>>3)&0x70); }

__device__ __forceinline__ void ldsm4(uint32_t* r, uint32_t addr){
    asm volatile("ldmatrix.sync.aligned.m8n8.x4.shared.b16 {%0,%1,%2,%3}, [%4];"
        : "=r"(r[0]),"=r"(r[1]),"=r"(r[2]),"=r"(r[3]) : "r"(addr));
}
__device__ __forceinline__ void mma16816(float* c, const uint32_t* a, uint32_t b0, uint32_t b1){
    asm volatile("mma.sync.aligned.m16n8k16.row.col.f32.bf16.bf16.f32 "
        "{%0,%1,%2,%3}, {%4,%5,%6,%7}, {%8,%9}, {%0,%1,%2,%3};"
        : "+f"(c[0]),"+f"(c[1]),"+f"(c[2]),"+f"(c[3])
        : "r"(a[0]),"r"(a[1]),"r"(a[2]),"r"(a[3]), "r"(b0),"r"(b1));
}

#define SMEM_DYN 65536

// ---------------------------------------------------------------------------
// bf16x3 NT warp-MMA GEMM: D[128,128] tile of scale*(A[M,K] . B[N,K]^T)
// A,B pre-split into hi/lo bf16. D = Ah*Bh + Ah*Bl + Al*Bh (fp32 accum).
// Block 256 thr = 8 warps (4 M x 2 N), warp tile 32x64, BK=64.
// EPI: 0 fp32 + scale + causal mask | 1 fp32 plain
//      2 split-bf16, off = gm*orow + local_col (Oh/Ol base pre-offset)
//      3 split-bf16 transposed, off = local_col*orow + gm
// ---------------------------------------------------------------------------
template<int EPI>
__device__ void gemm_mma(
    const __nv_bfloat16* __restrict__ Ah, const __nv_bfloat16* __restrict__ Al, int lda,
    const __nv_bfloat16* __restrict__ Bh, const __nv_bfloat16* __restrict__ Bl, int ldb,
    int kCount, int m0, int n0, float scale,
    float* __restrict__ Cf, int ldc,
    __nv_bfloat16* __restrict__ Oh, __nv_bfloat16* __restrict__ Ol, int orow)
{
    extern __shared__ char sm[];
    const int tid = threadIdx.x, lane = tid & 31, wid = tid >> 5;
    const int wm = wid & 3, wn = wid >> 2;
    const int g = lane >> 2, t4 = lane & 3;

    const uint32_t sbase = smem_u32(sm);
    // tiles: Ah @0, Al @16K, Bh @32K, Bl @48K (each 128 rows x 128B, SW128 swizzled)
    const int mtx = lane >> 3, ri = lane & 7;
    const int lrow = ((mtx & 1) << 3) + ri;   // row within 16-row group
    const int lkh  = mtx >> 1;                // k-half chunk

    float acc[64];
#pragma unroll
    for (int i = 0; i < 64; i++) acc[i] = 0.f;

    for (int k0 = 0; k0 < kCount; k0 += 64) {
        __syncthreads();
        // ---- global -> smem (coalesced 128B rows, swizzled 16B chunks)
        {
            const __nv_bfloat16* srcs[4] = {Ah, Al, Bh, Bl};
            const int lds[4] = {lda, lda, ldb, ldb};
            const int r0s[4] = {m0, m0, n0, n0};
#pragma unroll
            for (int p = 0; p < 4; p++) {
#pragma unroll
                for (int i = 0; i < 4; i++) {
                    int lin = tid + i * 256;
                    int r = lin >> 3, ch = lin & 7;
                    uint4 v = *reinterpret_cast<const uint4*>(
                        srcs[p] + (size_t)(r0s[p] + r) * lds[p] + k0 + ch * 8);
                    *reinterpret_cast<uint4*>(sm + p * 16384 + swz(r * 128 + ch * 16)) = v;
                }
            }
        }
        __syncthreads();

#pragma unroll
        for (int kk = 0; kk < 4; kk++) {
            const int chb = (kk * 2 + lkh) * 16;
            uint32_t aH[8], aL[8];
#pragma unroll
            for (int s = 0; s < 2; s++) {
                uint32_t off = swz((uint32_t)(wm * 32 + s * 16 + lrow) * 128 + chb);
                ldsm4(aH + s * 4, sbase + off);            // Ah tile @0
                ldsm4(aL + s * 4, sbase + 16384 + off);    // Al tile
            }
#pragma unroll
            for (int nb = 0; nb < 4; nb++) {
                uint32_t off = swz((uint32_t)(wn * 64 + nb * 16 + lrow) * 128 + chb);
                uint32_t bh[4], bl[4];
                ldsm4(bh, sbase + 32768 + off);
                ldsm4(bl, sbase + 49152 + off);
#pragma unroll
                for (int mi = 0; mi < 2; mi++) {
#pragma unroll
                    for (int sub = 0; sub < 2; sub++) {
                        float* c = acc + (mi * 8 + nb * 2 + sub) * 4;
                        mma16816(c, aH + mi * 4, bh[sub], bh[sub + 2]);
                        mma16816(c, aH + mi * 4, bl[sub], bl[sub + 2]);
                        mma16816(c, aL + mi * 4, bh[sub], bh[sub + 2]);
                    }
                }
            }
        }
    }

    // ---- epilogue straight from registers
#pragma unroll
    for (int mi = 0; mi < 2; mi++) {
#pragma unroll
        for (int nbi = 0; nbi < 8; nbi++) {
            const float* c = acc + (mi * 8 + nbi) * 4;
            int rl = wm * 32 + mi * 16 + g;       // local row (and rl+8)
            int cl = wn * 64 + nbi * 8 + 2 * t4;  // local col (even)
            if (EPI <= 1) {
                int gr0 = m0 + rl, gc = n0 + cl;
                float v0 = c[0] * scale, v1 = c[1] * scale;
                float v2 = c[2] * scale, v3 = c[3] * scale;
                if (EPI == 0) {
                    if (gc     > gr0)     v0 = -CUDART_INF_F;
                    if (gc + 1 > gr0)     v1 = -CUDART_INF_F;
                    if (gc     > gr0 + 8) v2 = -CUDART_INF_F;
                    if (gc + 1 > gr0 + 8) v3 = -CUDART_INF_F;
                }
                *reinterpret_cast<float2*>(Cf + (size_t)gr0 * ldc + gc)       = make_float2(v0, v1);
                *reinterpret_cast<float2*>(Cf + (size_t)(gr0 + 8) * ldc + gc) = make_float2(v2, v3);
            } else {
                __nv_bfloat16 h0 = __float2bfloat16(c[0]);
                __nv_bfloat16 h1 = __float2bfloat16(c[1]);
                __nv_bfloat16 h2 = __float2bfloat16(c[2]);
                __nv_bfloat16 h3 = __float2bfloat16(c[3]);
                __nv_bfloat16 l0 = __float2bfloat16(c[0] - __bfloat162float(h0));
                __nv_bfloat16 l1 = __float2bfloat16(c[1] - __bfloat162float(h1));
                __nv_bfloat16 l2 = __float2bfloat16(c[2] - __bfloat162float(h2));
                __nv_bfloat16 l3 = __float2bfloat16(c[3] - __bfloat162float(h3));
                size_t gm = (size_t)(m0 + rl);
                if (EPI == 2) {
                    size_t o0 = gm * orow + cl, o1 = o0 + (size_t)8 * orow;
                    *reinterpret_cast<__nv_bfloat162*>(Oh + o0) = __nv_bfloat162(h0, h1);
                    *reinterpret_cast<__nv_bfloat162*>(Ol + o0) = __nv_bfloat162(l0, l1);
                    *reinterpret_cast<__nv_bfloat162*>(Oh + o1) = __nv_bfloat162(h2, h3);
                    *reinterpret_cast<__nv_bfloat162*>(Ol + o1) = __nv_bfloat162(l2, l3);
                } else {
                    size_t c0 = (size_t)cl * orow, c1 = (size_t)(cl + 1) * orow;
                    Oh[c0 + gm]     = h0; Oh[c1 + gm]     = h1;
                    Oh[c0 + gm + 8] = h2; Oh[c1 + gm + 8] = h3;
                    Ol[c0 + gm]     = l0; Ol[c1 + gm]     = l1;
                    Ol[c0 + gm + 8] = l2; Ol[c1 + gm + 8] = l3;
                }
            }
        }
    }
}

// ---------------------------------------------------------------------------
__global__ void __launch_bounds__(256) k_split(
    const float* __restrict__ s, __nv_bfloat16* __restrict__ h,
    __nv_bfloat16* __restrict__ l, int n4)
{
    int i = blockIdx.x * blockDim.x + threadIdx.x;
    if (i >= n4) return;
    float4 v = reinterpret_cast<const float4*>(s)[i];
    __nv_bfloat16 h0=__float2bfloat16(v.x), h1=__float2bfloat16(v.y),
                  h2=__float2bfloat16(v.z), h3=__float2bfloat16(v.w);
    __nv_bfloat16 l0=__float2bfloat16(v.x-__bfloat162float(h0)),
                  l1=__float2bfloat16(v.y-__bfloat162float(h1)),
                  l2=__float2bfloat16(v.z-__bfloat162float(h2)),
                  l3=__float2bfloat16(v.w-__bfloat162float(h3));
    uint2 hv = make_uint2((uint32_t)__bfloat16_as_ushort(h0)|((uint32_t)__bfloat16_as_ushort(h1)<<16),
                          (uint32_t)__bfloat16_as_ushort(h2)|((uint32_t)__bfloat16_as_ushort(h3)<<16));
    uint2 lv = make_uint2((uint32_t)__bfloat16_as_ushort(l0)|((uint32_t)__bfloat16_as_ushort(l1)<<16),
                          (uint32_t)__bfloat16_as_ushort(l2)|((uint32_t)__bfloat16_as_ushort(l3)<<16));
    reinterpret_cast<uint2*>(h)[i] = hv;
    reinterpret_cast<uint2*>(l)[i] = lv;
}

__global__ void __launch_bounds__(256, 2) k_qkv_mma(void)
{
    int n0 = blockIdx.x * 128, m0 = blockIdx.y * 128, z = blockIdx.z;
    int b = m0 >> 11, h = n0 >> 9, e0 = n0 & 511;
    const __nv_bfloat16 *Wh, *Wl;
    if (z == 0)      { Wh = g_wqh; Wl = g_wql; }
    else if (z == 1) { Wh = g_wkh; Wl = g_wkl; }
    else             { Wh = g_wvh; Wl = g_wvl; }
    if (z < 2) {
        size_t base = ((size_t)(b*16384 + h*2048) << 9) + e0 - ((size_t)(b*2048) << 9);
        __nv_bfloat16* OH = (z == 0 ? g_qh : g_kh) + base;
        __nv_bfloat16* OL = (z == 0 ? g_ql : g_kl) + base;
        gemm_mma<2>(g_xh, g_xl, 512, Wh, Wl, 512, 512, m0, n0, 1.f,
                    nullptr, 0, OH, OL, 512);
    } else {
        size_t base = ((size_t)(b*4096 + h*512 + e0) << 11) - (size_t)b * 2048;
        gemm_mma<3>(g_xh, g_xl, 512, Wh, Wl, 512, 512, m0, n0, 1.f,
                    nullptr, 0, g_vth + base, g_vtl + base, 2048);
    }
}

__global__ void __launch_bounds__(256, 2) k_scores_mma(void)
{
    int bh = blockIdx.z, n0 = blockIdx.x * 128, m0 = blockIdx.y * 128;
    float* Cf = g_s + (size_t)bh * SS * SS;
    if (n0 > m0) {   // tile fully above diagonal: -inf fill
        float4 o = make_float4(-CUDART_INF_F, -CUDART_INF_F, -CUDART_INF_F, -CUDART_INF_F);
        for (int idx = threadIdx.x; idx < 128 * 32; idx += 256) {
            int row = idx >> 5, c4 = idx & 31;
            *reinterpret_cast<float4*>(Cf + (size_t)(m0 + row) * SS + n0 + c4 * 4) = o;
        }
        return;
    }
    size_t ob = (size_t)bh * SS * DK;
    gemm_mma<0>(g_qh + ob, g_ql + ob, 512, g_kh + ob, g_kl + ob, 512,
                512, m0, n0, 0.04419417382415922f, Cf, SS, nullptr, nullptr, 0);
}

__global__ void __launch_bounds__(256) k_softmax(void)
{
    int row  = blockIdx.x * 8 + (threadIdx.x >> 5);
    int lane = threadIdx.x & 31;
    const float4* p = reinterpret_cast<const float4*>(g_s + (size_t)row * SS);
    uint2* ph = reinterpret_cast<uint2*>(g_ph + (size_t)row * SS);
    uint2* pl = reinterpret_cast<uint2*>(g_pl + (size_t)row * SS);

    float4 v[16];
    float mx = -CUDART_INF_F;
#pragma unroll
    for (int i = 0; i < 16; i++) {
        v[i] = p[lane + i * 32];
        mx = fmaxf(mx, fmaxf(fmaxf(v[i].x, v[i].y), fmaxf(v[i].z, v[i].w)));
    }
#pragma unroll
    for (int o = 16; o; o >>= 1) mx = fmaxf(mx, __shfl_xor_sync(0xffffffffu, mx, o));
    float sum = 0.0f;
#pragma unroll
    for (int i = 0; i < 16; i++) {
        v[i].x = __expf(v[i].x - mx); v[i].y = __expf(v[i].y - mx);
        v[i].z = __expf(v[i].z - mx); v[i].w = __expf(v[i].w - mx);
        sum += (v[i].x + v[i].y) + (v[i].z + v[i].w);
    }
#pragma unroll
    for (int o = 16; o; o >>= 1) sum += __shfl_xor_sync(0xffffffffu, sum, o);
    float inv = 1.0f / sum;
#pragma unroll
    for (int i = 0; i < 16; i++) {
        float a0 = v[i].x*inv, a1 = v[i].y*inv, a2 = v[i].z*inv, a3 = v[i].w*inv;
        __nv_bfloat16 h0=__float2bfloat16(a0), h1=__float2bfloat16(a1),
                      h2=__float2bfloat16(a2), h3=__float2bfloat16(a3);
        __nv_bfloat16 l0=__float2bfloat16(a0-__bfloat162float(h0)),
                      l1=__float2bfloat16(a1-__bfloat162float(h1)),
                      l2=__float2bfloat16(a2-__bfloat162float(h2)),
                      l3=__float2bfloat16(a3-__bfloat162float(h3));
        ph[lane + i*32] = make_uint2(
            (uint32_t)__bfloat16_as_ushort(h0)|((uint32_t)__bfloat16_as_ushort(h1)<<16),
            (uint32_t)__bfloat16_as_ushort(h2)|((uint32_t)__bfloat16_as_ushort(h3)<<16));
        pl[lane + i*32] = make_uint2(
            (uint32_t)__bfloat16_as_ushort(l0)|((uint32_t)__bfloat16_as_ushort(l1)<<16),
            (uint32_t)__bfloat16_as_ushort(l2)|((uint32_t)__bfloat16_as_ushort(l3)<<16));
    }
}

__global__ void __launch_bounds__(256, 2) k_pv_mma(void)
{
    int bh = blockIdx.z, b = bh >> 3, h = bh & 7;
    int m0 = blockIdx.y * 128, n0 = blockIdx.x * 128;
    const __nv_bfloat16* Ah = g_ph + (size_t)bh * SS * SS;
    const __nv_bfloat16* Al = g_pl + (size_t)bh * SS * SS;
    const __nv_bfloat16* Bh = g_vth + (size_t)bh * DK * SS;
    const __nv_bfloat16* Bl = g_vtl + (size_t)bh * DK * SS;
    size_t base = (size_t)b * 2048 * 4096 + h * 512 + n0;
    gemm_mma<2>(Ah, Al, SS, Bh, Bl, SS, m0 + 128, m0, n0, 1.f,
                nullptr, 0, g_hoh + base, g_hol + base, 4096);
}

__global__ void __launch_bounds__(256, 2) k_out_mma(float* __restrict__ out)
{
    int m0 = blockIdx.y * 128, n0 = blockIdx.x * 128;
    gemm_mma<1>(g_hoh, g_hol, 4096, g_wuh, g_wul, 4096, 4096, m0, n0, 1.f,
                out, 512, nullptr, nullptr, 0);
}

// ---------------------------------------------------------------------------
extern "C" void kernel_launch(void* const* d_in, const int* in_sizes, int n_in,
                              void* d_out, int out_size)
{
    const float* x  = (const float*)d_in[0];
    const float* Wq = (const float*)d_in[1];
    const float* Wk = (const float*)d_in[2];
    const float* Wv = (const float*)d_in[3];
    const float* Wu = (const float*)d_in[4];
    float* out = (float*)d_out;

    cudaFuncSetAttribute(k_qkv_mma,    cudaFuncAttributeMaxDynamicSharedMemorySize, SMEM_DYN);
    cudaFuncSetAttribute(k_scores_mma, cudaFuncAttributeMaxDynamicSharedMemorySize, SMEM_DYN);
    cudaFuncSetAttribute(k_pv_mma,     cudaFuncAttributeMaxDynamicSharedMemorySize, SMEM_DYN);
    cudaFuncSetAttribute(k_out_mma,    cudaFuncAttributeMaxDynamicSharedMemorySize, SMEM_DYN);

    __nv_bfloat16 *xh, *xl, *wqh, *wql, *wkh, *wkl, *wvh, *wvl, *wuh, *wul;
    cudaGetSymbolAddress((void**)&xh,  g_xh);  cudaGetSymbolAddress((void**)&xl,  g_xl);
    cudaGetSymbolAddress((void**)&wqh, g_wqh); cudaGetSymbolAddress((void**)&wql, g_wql);
    cudaGetSymbolAddress((void**)&wkh, g_wkh); cudaGetSymbolAddress((void**)&wkl, g_wkl);
    cudaGetSymbolAddress((void**)&wvh, g_wvh); cudaGetSymbolAddress((void**)&wvl, g_wvl);
    cudaGetSymbolAddress((void**)&wuh, g_wuh); cudaGetSymbolAddress((void**)&wul, g_wul);

    const int n4 = TT * DK / 4;           // 524288 float4s per 4096x512 array
    k_split<<<(n4 + 255) / 256, 256>>>(x,  xh,  xl,  n4);
    k_split<<<(n4 + 255) / 256, 256>>>(Wq, wqh, wql, n4);
    k_split<<<(n4 + 255) / 256, 256>>>(Wk, wkh, wkl, n4);
    k_split<<<(n4 + 255) / 256, 256>>>(Wv, wvh, wvl, n4);
    k_split<<<(n4 + 255) / 256, 256>>>(Wu, wuh, wul, n4);

    k_qkv_mma   <<<dim3(32, 32, 3),  256, SMEM_DYN>>>();
    k_scores_mma<<<dim3(16, 16, NH), 256, SMEM_DYN>>>();
    k_softmax   <<<NH * SS / 8, 256>>>();
    k_pv_mma    <<<dim3(4, 16, NH),  256, SMEM_DYN>>>();
    k_out_mma   <<<dim3(4, 32, 1),   256, SMEM_DYN>>>(out);
}

// round 4
// speedup vs baseline: 2.4312x; 1.1686x over previous
#include <cuda_runtime.h>
#include <cuda_bf16.h>
#include <math_constants.h>
#include <cstdint>

#define BB 2
#define SS 2048
#define HH 8
#define DK 512
#define TT (BB*SS)      // 4096 tokens
#define NH (BB*HH)      // 16 (b,h) pairs

// ---------------- static device scratch (no allocs allowed) ----------------
__device__ __nv_bfloat16 g_xh[TT*DK],  g_xl[TT*DK];
__device__ __nv_bfloat16 g_wqh[4096*512], g_wql[4096*512];
__device__ __nv_bfloat16 g_wkh[4096*512], g_wkl[4096*512];
__device__ __nv_bfloat16 g_wvh[4096*512], g_wvl[4096*512];
__device__ __nv_bfloat16 g_wuh[512*4096], g_wul[512*4096];
__device__ __nv_bfloat16 g_qh[NH*SS*DK], g_ql[NH*SS*DK];
__device__ __nv_bfloat16 g_kh[NH*SS*DK], g_kl[NH*SS*DK];
__device__ __nv_bfloat16 g_vth[NH*DK*SS], g_vtl[NH*DK*SS];   // V transposed [bh][e][s]
__device__ float         g_s [(size_t)NH*SS*SS];             // fp32 scores (lower tri only)
__device__ __nv_bfloat16 g_ph[(size_t)NH*SS*SS], g_pl[(size_t)NH*SS*SS];
__device__ __nv_bfloat16 g_hoh[(size_t)TT*4096], g_hol[(size_t)TT*4096];

// ---------------- helpers (baseline ISA: ldmatrix + mma.sync + cp.async) ---
__device__ __forceinline__ uint32_t smem_u32(const void* p){
    uint32_t a; asm("{ .reg .u64 t; cvta.to.shared.u64 t, %1; cvt.u32.u64 %0, t; }":"=r"(a):"l"(p)); return a;
}
__device__ __forceinline__ uint32_t swz(uint32_t off){ return off ^ ((off>>3)&0x70); }

__device__ __forceinline__ void ldsm4(uint32_t* r, uint32_t addr){
    asm volatile("ldmatrix.sync.aligned.m8n8.x4.shared.b16 {%0,%1,%2,%3}, [%4];"
        : "=r"(r[0]),"=r"(r[1]),"=r"(r[2]),"=r"(r[3]) : "r"(addr));
}
__device__ __forceinline__ void mma16816(float* c, const uint32_t* a, uint32_t b0, uint32_t b1){
    asm volatile("mma.sync.aligned.m16n8k16.row.col.f32.bf16.bf16.f32 "
        "{%0,%1,%2,%3}, {%4,%5,%6,%7}, {%8,%9}, {%0,%1,%2,%3};"
        : "+f"(c[0]),"+f"(c[1]),"+f"(c[2]),"+f"(c[3])
        : "r"(a[0]),"r"(a[1]),"r"(a[2]),"r"(a[3]), "r"(b0),"r"(b1));
}
__device__ __forceinline__ void cp16(uint32_t dst, const void* src){
    asm volatile("cp.async.cg.shared.global [%0], [%1], 16;" :: "r"(dst), "l"(src) : "memory");
}
#define CP_COMMIT() asm volatile("cp.async.commit_group;" ::: "memory")
template<int N> __device__ __forceinline__ void cp_wait(){
    asm volatile("cp.async.wait_group %0;" :: "n"(N) : "memory");
}

#define STAGE 65536u        // 4 parts x 16KB per stage
#define SMEM_DYN 131072     // 2 stages

// ---------------------------------------------------------------------------
// bf16x3 NT warp-MMA GEMM with cp.async double buffering.
// D[128,128] tile of scale*(A[M,K] . B[N,K]^T); D = Ah*Bh + Ah*Bl + Al*Bh.
// Block 256 thr = 8 warps (4 M x 2 N), warp tile 32x64, BK=64.
// EPI: 0 fp32 + scale + causal mask | 1 fp32 plain
//      2 split-bf16, off = gm*orow + local_col | 3 split-bf16 transposed
// ---------------------------------------------------------------------------
template<int EPI>
__device__ void gemm_mma(
    const __nv_bfloat16* __restrict__ Ah, const __nv_bfloat16* __restrict__ Al, int lda,
    const __nv_bfloat16* __restrict__ Bh, const __nv_bfloat16* __restrict__ Bl, int ldb,
    int kCount, int m0, int n0, float scale,
    float* __restrict__ Cf, int ldc,
    __nv_bfloat16* __restrict__ Oh, __nv_bfloat16* __restrict__ Ol, int orow)
{
    extern __shared__ char sm[];
    const int tid = threadIdx.x, lane = tid & 31, wid = tid >> 5;
    const int wm = wid & 3, wn = wid >> 2;
    const int g = lane >> 2, t4 = lane & 3;
    const uint32_t sbase = smem_u32(sm);

    const int mtx = lane >> 3, ri = lane & 7;
    const int lrow = ((mtx & 1) << 3) + ri;   // row within 16-row group
    const int lkh  = mtx >> 1;                // k-half chunk

    // per-thread load coords (4 uint4 per part per chunk)
    const int lr0 = tid >> 3;        // +32*i
    const int lch = tid & 7;
    const __nv_bfloat16* srcs[4] = {Ah, Al, Bh, Bl};
    const int lds4[4] = {lda, lda, ldb, ldb};
    const int r0s[4]  = {m0, m0, n0, n0};

    float acc[64];
#pragma unroll
    for (int i = 0; i < 64; i++) acc[i] = 0.f;

    const int nk = kCount >> 6;

    // prefetch chunk 0 into stage 0
#pragma unroll
    for (int p = 0; p < 4; p++)
#pragma unroll
        for (int i = 0; i < 4; i++) {
            int r = lr0 + i * 32;
            cp16(sbase + p * 16384 + swz(r * 128 + lch * 16),
                 srcs[p] + (size_t)(r0s[p] + r) * lds4[p] + lch * 8);
        }
    CP_COMMIT();

    for (int kc = 0; kc < nk; kc++) {
        if (kc + 1 < nk) {
            const uint32_t sb = sbase + ((kc + 1) & 1) * STAGE;
            const int k0n = (kc + 1) << 6;
#pragma unroll
            for (int p = 0; p < 4; p++)
#pragma unroll
                for (int i = 0; i < 4; i++) {
                    int r = lr0 + i * 32;
                    cp16(sb + p * 16384 + swz(r * 128 + lch * 16),
                         srcs[p] + (size_t)(r0s[p] + r) * lds4[p] + k0n + lch * 8);
                }
            CP_COMMIT();
            cp_wait<1>();
        } else {
            cp_wait<0>();
        }
        __syncthreads();

        const uint32_t cb = sbase + (kc & 1) * STAGE;
#pragma unroll
        for (int kk = 0; kk < 4; kk++) {
            const int chb = (kk * 2 + lkh) * 16;
            uint32_t aH[8], aL[8];
#pragma unroll
            for (int s = 0; s < 2; s++) {
                uint32_t off = swz((uint32_t)(wm * 32 + s * 16 + lrow) * 128 + chb);
                ldsm4(aH + s * 4, cb + off);
                ldsm4(aL + s * 4, cb + 16384 + off);
            }
#pragma unroll
            for (int nb = 0; nb < 4; nb++) {
                uint32_t off = swz((uint32_t)(wn * 64 + nb * 16 + lrow) * 128 + chb);
                uint32_t bh[4], bl[4];
                ldsm4(bh, cb + 32768 + off);
                ldsm4(bl, cb + 49152 + off);
#pragma unroll
                for (int mi = 0; mi < 2; mi++) {
#pragma unroll
                    for (int sub = 0; sub < 2; sub++) {
                        float* c = acc + (mi * 8 + nb * 2 + sub) * 4;
                        mma16816(c, aH + mi * 4, bh[sub], bh[sub + 2]);
                        mma16816(c, aH + mi * 4, bl[sub], bl[sub + 2]);
                        mma16816(c, aL + mi * 4, bh[sub], bh[sub + 2]);
                    }
                }
            }
        }
        __syncthreads();
    }

    // ---- epilogue straight from registers
#pragma unroll
    for (int mi = 0; mi < 2; mi++) {
#pragma unroll
        for (int nbi = 0; nbi < 8; nbi++) {
            const float* c = acc + (mi * 8 + nbi) * 4;
            int rl = wm * 32 + mi * 16 + g;       // local row (and rl+8)
            int cl = wn * 64 + nbi * 8 + 2 * t4;  // local col (even)
            if (EPI <= 1) {
                int gr0 = m0 + rl, gc = n0 + cl;
                float v0 = c[0] * scale, v1 = c[1] * scale;
                float v2 = c[2] * scale, v3 = c[3] * scale;
                if (EPI == 0) {
                    if (gc     > gr0)     v0 = -CUDART_INF_F;
                    if (gc + 1 > gr0)     v1 = -CUDART_INF_F;
                    if (gc     > gr0 + 8) v2 = -CUDART_INF_F;
                    if (gc + 1 > gr0 + 8) v3 = -CUDART_INF_F;
                }
                *reinterpret_cast<float2*>(Cf + (size_t)gr0 * ldc + gc)       = make_float2(v0, v1);
                *reinterpret_cast<float2*>(Cf + (size_t)(gr0 + 8) * ldc + gc) = make_float2(v2, v3);
            } else {
                __nv_bfloat16 h0 = __float2bfloat16(c[0]);
                __nv_bfloat16 h1 = __float2bfloat16(c[1]);
                __nv_bfloat16 h2 = __float2bfloat16(c[2]);
                __nv_bfloat16 h3 = __float2bfloat16(c[3]);
                __nv_bfloat16 l0 = __float2bfloat16(c[0] - __bfloat162float(h0));
                __nv_bfloat16 l1 = __float2bfloat16(c[1] - __bfloat162float(h1));
                __nv_bfloat16 l2 = __float2bfloat16(c[2] - __bfloat162float(h2));
                __nv_bfloat16 l3 = __float2bfloat16(c[3] - __bfloat162float(h3));
                size_t gm = (size_t)(m0 + rl);
                if (EPI == 2) {
                    size_t o0 = gm * orow + cl, o1 = o0 + (size_t)8 * orow;
                    *reinterpret_cast<__nv_bfloat162*>(Oh + o0) = __nv_bfloat162(h0, h1);
                    *reinterpret_cast<__nv_bfloat162*>(Ol + o0) = __nv_bfloat162(l0, l1);
                    *reinterpret_cast<__nv_bfloat162*>(Oh + o1) = __nv_bfloat162(h2, h3);
                    *reinterpret_cast<__nv_bfloat162*>(Ol + o1) = __nv_bfloat162(l2, l3);
                } else {
                    size_t c0 = (size_t)cl * orow, c1 = (size_t)(cl + 1) * orow;
                    Oh[c0 + gm]     = h0; Oh[c1 + gm]     = h1;
                    Oh[c0 + gm + 8] = h2; Oh[c1 + gm + 8] = h3;
                    Ol[c0 + gm]     = l0; Ol[c1 + gm]     = l1;
                    Ol[c0 + gm + 8] = l2; Ol[c1 + gm + 8] = l3;
                }
            }
        }
    }
}

// ---------------------------------------------------------------------------
__global__ void __launch_bounds__(256) k_split(
    const float* __restrict__ s, __nv_bfloat16* __restrict__ h,
    __nv_bfloat16* __restrict__ l, int n4)
{
    int i = blockIdx.x * blockDim.x + threadIdx.x;
    if (i >= n4) return;
    float4 v = reinterpret_cast<const float4*>(s)[i];
    __nv_bfloat16 h0=__float2bfloat16(v.x), h1=__float2bfloat16(v.y),
                  h2=__float2bfloat16(v.z), h3=__float2bfloat16(v.w);
    __nv_bfloat16 l0=__float2bfloat16(v.x-__bfloat162float(h0)),
                  l1=__float2bfloat16(v.y-__bfloat162float(h1)),
                  l2=__float2bfloat16(v.z-__bfloat162float(h2)),
                  l3=__float2bfloat16(v.w-__bfloat162float(h3));
    uint2 hv = make_uint2((uint32_t)__bfloat16_as_ushort(h0)|((uint32_t)__bfloat16_as_ushort(h1)<<16),
                          (uint32_t)__bfloat16_as_ushort(h2)|((uint32_t)__bfloat16_as_ushort(h3)<<16));
    uint2 lv = make_uint2((uint32_t)__bfloat16_as_ushort(l0)|((uint32_t)__bfloat16_as_ushort(l1)<<16),
                          (uint32_t)__bfloat16_as_ushort(l2)|((uint32_t)__bfloat16_as_ushort(l3)<<16));
    reinterpret_cast<uint2*>(h)[i] = hv;
    reinterpret_cast<uint2*>(l)[i] = lv;
}

__global__ void __launch_bounds__(256) k_qkv_mma(void)
{
    int n0 = blockIdx.x * 128, m0 = blockIdx.y * 128, z = blockIdx.z;
    int b = m0 >> 11, h = n0 >> 9, e0 = n0 & 511;
    const __nv_bfloat16 *Wh, *Wl;
    if (z == 0)      { Wh = g_wqh; Wl = g_wql; }
    else if (z == 1) { Wh = g_wkh; Wl = g_wkl; }
    else             { Wh = g_wvh; Wl = g_wvl; }
    if (z < 2) {
        size_t base = ((size_t)(b*16384 + h*2048) << 9) + e0 - ((size_t)(b*2048) << 9);
        __nv_bfloat16* OH = (z == 0 ? g_qh : g_kh) + base;
        __nv_bfloat16* OL = (z == 0 ? g_ql : g_kl) + base;
        gemm_mma<2>(g_xh, g_xl, 512, Wh, Wl, 512, 512, m0, n0, 1.f,
                    nullptr, 0, OH, OL, 512);
    } else {
        size_t base = ((size_t)(b*4096 + h*512 + e0) << 11) - (size_t)b * 2048;
        gemm_mma<3>(g_xh, g_xl, 512, Wh, Wl, 512, 512, m0, n0, 1.f,
                    nullptr, 0, g_vth + base, g_vtl + base, 2048);
    }
}

__global__ void __launch_bounds__(256) k_scores_mma(void)
{
    int bh = blockIdx.z, n0 = blockIdx.x * 128, m0 = blockIdx.y * 128;
    if (n0 > m0) return;   // fully masked tile: never written, never read
    float* Cf = g_s + (size_t)bh * SS * SS;
    size_t ob = (size_t)bh * SS * DK;
    gemm_mma<0>(g_qh + ob, g_ql + ob, 512, g_kh + ob, g_kl + ob, 512,
                512, m0, n0, 0.04419417382415922f, Cf, SS, nullptr, nullptr, 0);
}

// Softmax over valid (causal) prefix only. Block i of 16 covers cols
// [128i, 128i+128) for this row; only blocks i <= r>>7 are read/written.
__global__ void __launch_bounds__(256) k_softmax(void)
{
    int row  = blockIdx.x * 8 + (threadIdx.x >> 5);
    int lane = threadIdx.x & 31;
    int r    = row & (SS - 1);
    int rt   = r >> 7;             // last valid 128-col block
    const float4* p = reinterpret_cast<const float4*>(g_s + (size_t)row * SS);
    uint2* ph = reinterpret_cast<uint2*>(g_ph + (size_t)row * SS);
    uint2* pl = reinterpret_cast<uint2*>(g_pl + (size_t)row * SS);

    float4 v[16];
    float mx = -CUDART_INF_F;
#pragma unroll
    for (int i = 0; i < 16; i++) {
        if (i <= rt) {
            v[i] = p[lane + i * 32];
            mx = fmaxf(mx, fmaxf(fmaxf(v[i].x, v[i].y), fmaxf(v[i].z, v[i].w)));
        } else {
            v[i] = make_float4(-CUDART_INF_F, -CUDART_INF_F, -CUDART_INF_F, -CUDART_INF_F);
        }
    }
#pragma unroll
    for (int o = 16; o; o >>= 1) mx = fmaxf(mx, __shfl_xor_sync(0xffffffffu, mx, o));
    float sum = 0.0f;
#pragma unroll
    for (int i = 0; i < 16; i++) {
        if (i > rt) continue;
        v[i].x = __expf(v[i].x - mx); v[i].y = __expf(v[i].y - mx);
        v[i].z = __expf(v[i].z - mx); v[i].w = __expf(v[i].w - mx);
        sum += (v[i].x + v[i].y) + (v[i].z + v[i].w);
    }
#pragma unroll
    for (int o = 16; o; o >>= 1) sum += __shfl_xor_sync(0xffffffffu, sum, o);
    float inv = 1.0f / sum;
#pragma unroll
    for (int i = 0; i < 16; i++) {
        if (i > rt) continue;
        float a0 = v[i].x*inv, a1 = v[i].y*inv, a2 = v[i].z*inv, a3 = v[i].w*inv;
        __nv_bfloat16 h0=__float2bfloat16(a0), h1=__float2bfloat16(a1),
                      h2=__float2bfloat16(a2), h3=__float2bfloat16(a3);
        __nv_bfloat16 l0=__float2bfloat16(a0-__bfloat162float(h0)),
                      l1=__float2bfloat16(a1-__bfloat162float(h1)),
                      l2=__float2bfloat16(a2-__bfloat162float(h2)),
                      l3=__float2bfloat16(a3-__bfloat162float(h3));
        ph[lane + i*32] = make_uint2(
            (uint32_t)__bfloat16_as_ushort(h0)|((uint32_t)__bfloat16_as_ushort(h1)<<16),
            (uint32_t)__bfloat16_as_ushort(h2)|((uint32_t)__bfloat16_as_ushort(h3)<<16));
        pl[lane + i*32] = make_uint2(
            (uint32_t)__bfloat16_as_ushort(l0)|((uint32_t)__bfloat16_as_ushort(l1)<<16),
            (uint32_t)__bfloat16_as_ushort(l2)|((uint32_t)__bfloat16_as_ushort(l3)<<16));
    }
}

__global__ void __launch_bounds__(256) k_pv_mma(void)
{
    int bh = blockIdx.z, b = bh >> 3, h = bh & 7;
    int m0 = blockIdx.y * 128, n0 = blockIdx.x * 128;
    const __nv_bfloat16* Ah = g_ph + (size_t)bh * SS * SS;
    const __nv_bfloat16* Al = g_pl + (size_t)bh * SS * SS;
    const __nv_bfloat16* Bh = g_vth + (size_t)bh * DK * SS;
    const __nv_bfloat16* Bl = g_vtl + (size_t)bh * DK * SS;
    size_t base = (size_t)b * 2048 * 4096 + h * 512 + n0;
    gemm_mma<2>(Ah, Al, SS, Bh, Bl, SS, m0 + 128, m0, n0, 1.f,
                nullptr, 0, g_hoh + base, g_hol + base, 4096);
}

__global__ void __launch_bounds__(256) k_out_mma(float* __restrict__ out)
{
    int m0 = blockIdx.y * 128, n0 = blockIdx.x * 128;
    gemm_mma<1>(g_hoh, g_hol, 4096, g_wuh, g_wul, 4096, 4096, m0, n0, 1.f,
                out, 512, nullptr, nullptr, 0);
}

// ---------------------------------------------------------------------------
extern "C" void kernel_launch(void* const* d_in, const int* in_sizes, int n_in,
                              void* d_out, int out_size)
{
    const float* x  = (const float*)d_in[0];
    const float* Wq = (const float*)d_in[1];
    const float* Wk = (const float*)d_in[2];
    const float* Wv = (const float*)d_in[3];
    const float* Wu = (const float*)d_in[4];
    float* out = (float*)d_out;

    cudaFuncSetAttribute(k_qkv_mma,    cudaFuncAttributeMaxDynamicSharedMemorySize, SMEM_DYN);
    cudaFuncSetAttribute(k_scores_mma, cudaFuncAttributeMaxDynamicSharedMemorySize, SMEM_DYN);
    cudaFuncSetAttribute(k_pv_mma,     cudaFuncAttributeMaxDynamicSharedMemorySize, SMEM_DYN);
    cudaFuncSetAttribute(k_out_mma,    cudaFuncAttributeMaxDynamicSharedMemorySize, SMEM_DYN);

    __nv_bfloat16 *xh, *xl, *wqh, *wql, *wkh, *wkl, *wvh, *wvl, *wuh, *wul;
    cudaGetSymbolAddress((void**)&xh,  g_xh);  cudaGetSymbolAddress((void**)&xl,  g_xl);
    cudaGetSymbolAddress((void**)&wqh, g_wqh); cudaGetSymbolAddress((void**)&wql, g_wql);
    cudaGetSymbolAddress((void**)&wkh, g_wkh); cudaGetSymbolAddress((void**)&wkl, g_wkl);
    cudaGetSymbolAddress((void**)&wvh, g_wvh); cudaGetSymbolAddress((void**)&wvl, g_wvl);
    cudaGetSymbolAddress((void**)&wuh, g_wuh); cudaGetSymbolAddress((void**)&wul, g_wul);

    const int n4 = TT * DK / 4;           // 524288 float4s per 4096x512 array
    k_split<<<(n4 + 255) / 256, 256>>>(x,  xh,  xl,  n4);
    k_split<<<(n4 + 255) / 256, 256>>>(Wq, wqh, wql, n4);
    k_split<<<(n4 + 255) / 256, 256>>>(Wk, wkh, wkl, n4);
    k_split<<<(n4 + 255) / 256, 256>>>(Wv, wvh, wvl, n4);
    k_split<<<(n4 + 255) / 256, 256>>>(Wu, wuh, wul, n4);

    k_qkv_mma   <<<dim3(32, 32, 3),  256, SMEM_DYN>>>();
    k_scores_mma<<<dim3(16, 16, NH), 256, SMEM_DYN>>>();
    k_softmax   <<<NH * SS / 8, 256>>>();
    k_pv_mma    <<<dim3(4, 16, NH),  256, SMEM_DYN>>>();
    k_out_mma   <<<dim3(4, 32, 1),   256, SMEM_DYN>>>(out);
}